// round 3
// baseline (speedup 1.0000x reference)
#include <cuda_runtime.h>
#include <math.h>

#define NN    50000
#define EE    800000
#define ET    (EE + NN)      // 850000 edges incl. self loops
#define F1    256            // HEADS*HID
#define OUTC  128
#define NHEAD 4
#define NEG   0.2f

// ---------------- scratch (device globals; no allocation allowed) ----------
__device__ __align__(16) static float g_h1[(size_t)NN * F1];     // layer1 GEMM out; reused as layer2 GEMM input
__device__ __align__(16) static float g_out1[(size_t)NN * F1];   // layer1 aggregation
__device__ __align__(16) static float g_h2[(size_t)NN * OUTC];   // layer2 GEMM out
__device__ static float g_as1[NN * NHEAD], g_ad1[NN * NHEAD];
__device__ static float g_m1[NN * NHEAD], g_den1[NN * NHEAD];
__device__ static float g_as2[NN], g_ad2[NN], g_m2[NN], g_den2[NN];
__device__ static float g_alpha[(size_t)ET * NHEAD];             // per-(edge,head) softmax weight

// ---------------- helpers --------------------------------------------------
__device__ __forceinline__ void atomicMaxF(float* addr, float v) {
    if (v >= 0.0f) atomicMax((int*)addr, __float_as_int(v));
    else           atomicMin((unsigned int*)addr, __float_as_uint(v));
}

__device__ __forceinline__ void redAdd4(float* p, float a, float b, float c, float d) {
    asm volatile("red.global.add.v4.f32 [%0], {%1,%2,%3,%4};"
                 :: "l"(p), "f"(a), "f"(b), "f"(c), "f"(d) : "memory");
}

// edge_index is int32 (JAX x64 disabled => int64 request silently becomes int32)
__device__ __forceinline__ int2 get_edge(const int* __restrict__ ei, int e) {
    if (e < EE) return make_int2(ei[e], ei[EE + e]);
    int n = e - EE;
    return make_int2(n, n);   // self loop
}

// ---------------- init -----------------------------------------------------
__global__ void init_all() {
    int i = blockIdx.x * blockDim.x + threadIdx.x;
    if (i < NN * F1) g_out1[i] = 0.0f;
    if (i < NN * NHEAD) { g_den1[i] = 0.0f; g_m1[i] = __int_as_float(0xff800000); }
    if (i < NN)         { g_den2[i] = 0.0f; g_m2[i] = __int_as_float(0xff800000); }
}

__global__ void init_out(float* __restrict__ out, const float* __restrict__ b2) {
    int i = blockIdx.x * blockDim.x + threadIdx.x;
    if (i < NN * OUTC) out[i] = b2[i & (OUTC - 1)];
}

// ---------------- SGEMM: 128x128 tile, BK=8, 8x8 per thread ----------------
// LAYER 0:  g_h1 = x  @ W1   (K=128, P=256)
// LAYER 1:  g_h2 = g_h1 @ W2 (K=256, P=128)
template <int LAYER>
__global__ __launch_bounds__(256) void sgemm(const float* __restrict__ Aext,
                                             const float* __restrict__ B) {
    constexpr int K = (LAYER == 0) ? 128 : 256;
    constexpr int P = (LAYER == 0) ? 256 : 128;
    const float* A = (LAYER == 0) ? Aext : g_h1;
    float* C = (LAYER == 0) ? g_h1 : g_h2;

    __shared__ float As[8][128];
    __shared__ float Bs[8][128];

    const int tid = threadIdx.x;
    const int tx = tid & 15, ty = tid >> 4;
    const int rowBase = blockIdx.y * 128, colBase = blockIdx.x * 128;

    const int am = tid >> 1, ak = (tid & 1) * 4;     // A: 2 threads per row, float4
    const int bk = tid >> 5, bn = (tid & 31) * 4;    // B: coalesced float4

    float acc[8][8];
#pragma unroll
    for (int i = 0; i < 8; i++)
#pragma unroll
        for (int j = 0; j < 8; j++) acc[i][j] = 0.0f;

    for (int k0 = 0; k0 < K; k0 += 8) {
        float4 av = make_float4(0.f, 0.f, 0.f, 0.f);
        int arow = rowBase + am;
        if (arow < NN)
            av = *(const float4*)(A + (size_t)arow * K + k0 + ak);
        float4 bv = *(const float4*)(B + (size_t)(k0 + bk) * P + colBase + bn);

        __syncthreads();
        As[ak + 0][am] = av.x; As[ak + 1][am] = av.y;
        As[ak + 2][am] = av.z; As[ak + 3][am] = av.w;
        *(float4*)&Bs[bk][bn] = bv;
        __syncthreads();

#pragma unroll
        for (int kk = 0; kk < 8; kk++) {
            float4 a0 = *(const float4*)&As[kk][ty * 8];
            float4 a1 = *(const float4*)&As[kk][ty * 8 + 4];
            float4 b0 = *(const float4*)&Bs[kk][tx * 8];
            float4 b1 = *(const float4*)&Bs[kk][tx * 8 + 4];
            float a[8] = {a0.x, a0.y, a0.z, a0.w, a1.x, a1.y, a1.z, a1.w};
            float b[8] = {b0.x, b0.y, b0.z, b0.w, b1.x, b1.y, b1.z, b1.w};
#pragma unroll
            for (int i = 0; i < 8; i++)
#pragma unroll
                for (int j = 0; j < 8; j++) acc[i][j] += a[i] * b[j];
        }
    }

#pragma unroll
    for (int i = 0; i < 8; i++) {
        int r = rowBase + ty * 8 + i;
        if (r < NN) {
            float4 c0 = make_float4(acc[i][0], acc[i][1], acc[i][2], acc[i][3]);
            float4 c1 = make_float4(acc[i][4], acc[i][5], acc[i][6], acc[i][7]);
            *(float4*)(C + (size_t)r * P + colBase + tx * 8)     = c0;
            *(float4*)(C + (size_t)r * P + colBase + tx * 8 + 4) = c1;
        }
    }
}

// ---------------- per-node attention coefficients --------------------------
__global__ __launch_bounds__(256) void alphas1_k(const float* __restrict__ a_src,
                                                 const float* __restrict__ a_dst) {
    int warp = (blockIdx.x * blockDim.x + threadIdx.x) >> 5;
    int lane = threadIdx.x & 31;
    if (warp >= NN) return;
    const float* hp = g_h1 + (size_t)warp * F1;
#pragma unroll
    for (int hd = 0; hd < NHEAD; hd++) {
        float v0 = hp[hd * 64 + lane], v1 = hp[hd * 64 + 32 + lane];
        float s = v0 * a_src[hd * 64 + lane] + v1 * a_src[hd * 64 + 32 + lane];
        float d = v0 * a_dst[hd * 64 + lane] + v1 * a_dst[hd * 64 + 32 + lane];
#pragma unroll
        for (int o = 16; o; o >>= 1) {
            s += __shfl_down_sync(0xffffffffu, s, o);
            d += __shfl_down_sync(0xffffffffu, d, o);
        }
        if (lane == 0) { g_as1[warp * NHEAD + hd] = s; g_ad1[warp * NHEAD + hd] = d; }
    }
}

__global__ __launch_bounds__(256) void alphas2_k(const float* __restrict__ a_src,
                                                 const float* __restrict__ a_dst) {
    int warp = (blockIdx.x * blockDim.x + threadIdx.x) >> 5;
    int lane = threadIdx.x & 31;
    if (warp >= NN) return;
    const float* hp = g_h2 + (size_t)warp * OUTC;
    float s = 0.f, d = 0.f;
#pragma unroll
    for (int q = 0; q < 4; q++) {
        int c = lane + q * 32;
        float v = hp[c];
        s += v * a_src[c];
        d += v * a_dst[c];
    }
#pragma unroll
    for (int o = 16; o; o >>= 1) {
        s += __shfl_down_sync(0xffffffffu, s, o);
        d += __shfl_down_sync(0xffffffffu, d, o);
    }
    if (lane == 0) { g_as2[warp] = s; g_ad2[warp] = d; }
}

// ---------------- edge softmax passes --------------------------------------
template <int L>
__global__ __launch_bounds__(256) void edge_max(const int* __restrict__ ei) {
    constexpr int H = (L == 0) ? NHEAD : 1;
    int idx = blockIdx.x * blockDim.x + threadIdx.x;
    if (idx >= ET * H) return;
    int e = (L == 0) ? (idx >> 2) : idx;
    int hd = (L == 0) ? (idx & 3) : 0;
    int2 sd = get_edge(ei, e);
    const float* as_ = (L == 0) ? g_as1 : g_as2;
    const float* ad_ = (L == 0) ? g_ad1 : g_ad2;
    float* m_ = (L == 0) ? g_m1 : g_m2;
    float v = as_[sd.x * H + hd] + ad_[sd.y * H + hd];
    v = (v > 0.f) ? v : NEG * v;
    atomicMaxF(&m_[sd.y * H + hd], v);
}

template <int L>
__global__ __launch_bounds__(256) void edge_sum(const int* __restrict__ ei) {
    constexpr int H = (L == 0) ? NHEAD : 1;
    int idx = blockIdx.x * blockDim.x + threadIdx.x;
    if (idx >= ET * H) return;
    int e = (L == 0) ? (idx >> 2) : idx;
    int hd = (L == 0) ? (idx & 3) : 0;
    int2 sd = get_edge(ei, e);
    const float* as_ = (L == 0) ? g_as1 : g_as2;
    const float* ad_ = (L == 0) ? g_ad1 : g_ad2;
    const float* m_ = (L == 0) ? g_m1 : g_m2;
    float* den_ = (L == 0) ? g_den1 : g_den2;
    float v = as_[sd.x * H + hd] + ad_[sd.y * H + hd];
    v = (v > 0.f) ? v : NEG * v;
    float ex = __expf(v - m_[sd.y * H + hd]);
    g_alpha[idx] = ex;
    atomicAdd(&den_[sd.y * H + hd], ex);
}

template <int L>
__global__ __launch_bounds__(256) void edge_div(const int* __restrict__ ei) {
    constexpr int H = (L == 0) ? NHEAD : 1;
    int idx = blockIdx.x * blockDim.x + threadIdx.x;
    if (idx >= ET * H) return;
    int e = (L == 0) ? (idx >> 2) : idx;
    int hd = (L == 0) ? (idx & 3) : 0;
    int2 sd = get_edge(ei, e);
    const float* den_ = (L == 0) ? g_den1 : g_den2;
    g_alpha[idx] = g_alpha[idx] / den_[sd.y * H + hd];
}

// ---------------- aggregation: out[dst] += alpha * h[src] ------------------
template <int L>
__global__ __launch_bounds__(256) void edge_agg(const int* __restrict__ ei,
                                                float* __restrict__ outp) {
    constexpr int F = (L == 0) ? F1 : OUTC;
    constexpr int G = F / 4;                 // float4 groups per edge
    constexpr int SH = (L == 0) ? 6 : 5;
    constexpr int H = (L == 0) ? NHEAD : 1;
    int idx = blockIdx.x * blockDim.x + threadIdx.x;
    if (idx >= ET * G) return;
    int e = idx >> SH;
    int g = idx & (G - 1);
    int hd = (L == 0) ? (g >> 4) : 0;
    int2 sd = get_edge(ei, e);
    float alpha = g_alpha[e * H + hd];
    const float4* hsrc = (L == 0) ? (const float4*)g_h1 : (const float4*)g_h2;
    float4 hv = hsrc[(size_t)sd.x * G + g];
    float* op = ((L == 0) ? g_out1 : outp) + (size_t)sd.y * F + g * 4;
    redAdd4(op, alpha * hv.x, alpha * hv.y, alpha * hv.z, alpha * hv.w);
}

// ---------------- bias + ELU (layer1 epilogue -> layer2 input) -------------
__global__ __launch_bounds__(256) void bias_elu(const float* __restrict__ b1) {
    int i = blockIdx.x * blockDim.x + threadIdx.x;
    if (i >= NN * F1) return;
    float v = g_out1[i] + b1[i & (F1 - 1)];
    g_h1[i] = (v > 0.f) ? v : expm1f(v);
}

// ---------------- launch ---------------------------------------------------
extern "C" void kernel_launch(void* const* d_in, const int* in_sizes, int n_in,
                              void* d_out, int out_size) {
    const float* x   = (const float*)d_in[0];
    const int*   ei  = (const int*)d_in[1];      // int32 edge_index [2, E]
    const float* W1  = (const float*)d_in[2];
    const float* as1 = (const float*)d_in[3];
    const float* ad1 = (const float*)d_in[4];
    const float* b1  = (const float*)d_in[5];
    const float* W2  = (const float*)d_in[6];
    const float* as2 = (const float*)d_in[7];
    const float* ad2 = (const float*)d_in[8];
    const float* b2  = (const float*)d_in[9];
    float*       out = (float*)d_out;

    const int T = 256;
    init_all<<<(NN * F1 + T - 1) / T, T>>>();

    // ---- layer 1 ----
    sgemm<0><<<dim3(F1 / 128, (NN + 127) / 128), T>>>(x, W1);
    alphas1_k<<<(NN * 32 + T - 1) / T, T>>>(as1, ad1);
    edge_max<0><<<(ET * NHEAD + T - 1) / T, T>>>(ei);
    edge_sum<0><<<(ET * NHEAD + T - 1) / T, T>>>(ei);
    edge_div<0><<<(ET * NHEAD + T - 1) / T, T>>>(ei);
    edge_agg<0><<<(ET * (F1 / 4) + T - 1) / T, T>>>(ei, nullptr);
    bias_elu<<<(NN * F1 + T - 1) / T, T>>>(b1);

    // ---- layer 2 ----
    sgemm<1><<<dim3(OUTC / 128, (NN + 127) / 128), T>>>(x /*unused*/, W2);
    alphas2_k<<<(NN * 32 + T - 1) / T, T>>>(as2, ad2);
    edge_max<1><<<(ET + T - 1) / T, T>>>(ei);
    edge_sum<1><<<(ET + T - 1) / T, T>>>(ei);
    edge_div<1><<<(ET + T - 1) / T, T>>>(ei);
    init_out<<<(NN * OUTC + T - 1) / T, T>>>(out, b2);
    edge_agg<1><<<(ET * (OUTC / 4) + T - 1) / T, T>>>(ei, out);
}

// round 4
// speedup vs baseline: 1.1232x; 1.1232x over previous
#include <cuda_runtime.h>
#include <math.h>

#define NN    50000
#define EE    800000
#define ET    (EE + NN)      // edges incl. self loops
#define F1    256            // HEADS*HID
#define OUTC  128
#define NHEAD 4
#define NEG   0.2f
#define NINF  __int_as_float(0xff800000)

// ---------------- scratch (device globals; no allocation allowed) ----------
__device__ __align__(16) static float g_h1[(size_t)NN * F1];    // layer1 GEMM out
__device__ __align__(16) static float g_out1[(size_t)NN * F1];  // layer1 agg out (ELU'd) = layer2 GEMM in
__device__ __align__(16) static float g_h2[(size_t)NN * OUTC];  // layer2 GEMM out
__device__ __align__(16) static float g_as1[NN * NHEAD];
__device__ __align__(16) static float g_ad1[NN * NHEAD];
__device__ static float g_as2[NN], g_ad2[NN];
__device__ __align__(16) static float g_alpha[(size_t)ET * NHEAD]; // unnormalized exp weights
// CSR
__device__ static int g_cnt[NN], g_cnt2[NN];
__device__ static int g_off[NN + 1];
__device__ static int g_ssrc[ET];       // src node of each dst-sorted edge

// ---------------- CSR build ------------------------------------------------
__global__ void zero_cnt() {
    int i = blockIdx.x * blockDim.x + threadIdx.x;
    if (i < NN) { g_cnt[i] = 0; g_cnt2[i] = 0; }
}

__global__ void csr_count(const int* __restrict__ ei) {
    int e = blockIdx.x * blockDim.x + threadIdx.x;
    if (e >= ET) return;
    int dst = (e < EE) ? ei[EE + e] : (e - EE);
    atomicAdd(&g_cnt[dst], 1);
}

__global__ __launch_bounds__(1024) void csr_scan() {   // single block
    __shared__ int sp[1024];
    const int CH = (NN + 1023) / 1024;   // 49
    int t = threadIdx.x;
    int base = t * CH;
    int s = 0;
    for (int i = 0; i < CH; i++) { int j = base + i; if (j < NN) s += g_cnt[j]; }
    sp[t] = s;
    __syncthreads();
    for (int o = 1; o < 1024; o <<= 1) {
        int v = (t >= o) ? sp[t - o] : 0;
        __syncthreads();
        sp[t] += v;
        __syncthreads();
    }
    int p = sp[t] - s;    // exclusive prefix
    for (int i = 0; i < CH; i++) {
        int j = base + i;
        if (j < NN) { g_off[j] = p; p += g_cnt[j]; }
    }
    if (t == 1023) g_off[NN] = sp[1023];
}

__global__ void csr_scatter(const int* __restrict__ ei) {
    int e = blockIdx.x * blockDim.x + threadIdx.x;
    if (e >= ET) return;
    int src = (e < EE) ? ei[e]      : (e - EE);
    int dst = (e < EE) ? ei[EE + e] : (e - EE);
    int pos = g_off[dst] + atomicAdd(&g_cnt2[dst], 1);
    g_ssrc[pos] = src;
}

// ---------------- SGEMM: 128x128 tile, BK=8, 8x8 per thread ----------------
// LAYER 0:  g_h1 = x      @ W1  (K=128, P=256)
// LAYER 1:  g_h2 = g_out1 @ W2  (K=256, P=128)
template <int LAYER>
__global__ __launch_bounds__(256) void sgemm(const float* __restrict__ Aext,
                                             const float* __restrict__ B) {
    constexpr int K = (LAYER == 0) ? 128 : 256;
    constexpr int P = (LAYER == 0) ? 256 : 128;
    const float* A = (LAYER == 0) ? Aext : g_out1;
    float* C = (LAYER == 0) ? g_h1 : g_h2;

    __shared__ float As[8][128];
    __shared__ float Bs[8][128];

    const int tid = threadIdx.x;
    const int tx = tid & 15, ty = tid >> 4;
    const int rowBase = blockIdx.y * 128, colBase = blockIdx.x * 128;

    const int am = tid >> 1, ak = (tid & 1) * 4;
    const int bk = tid >> 5, bn = (tid & 31) * 4;

    float acc[8][8];
#pragma unroll
    for (int i = 0; i < 8; i++)
#pragma unroll
        for (int j = 0; j < 8; j++) acc[i][j] = 0.0f;

    for (int k0 = 0; k0 < K; k0 += 8) {
        float4 av = make_float4(0.f, 0.f, 0.f, 0.f);
        int arow = rowBase + am;
        if (arow < NN)
            av = *(const float4*)(A + (size_t)arow * K + k0 + ak);
        float4 bv = *(const float4*)(B + (size_t)(k0 + bk) * P + colBase + bn);

        __syncthreads();
        As[ak + 0][am] = av.x; As[ak + 1][am] = av.y;
        As[ak + 2][am] = av.z; As[ak + 3][am] = av.w;
        *(float4*)&Bs[bk][bn] = bv;
        __syncthreads();

#pragma unroll
        for (int kk = 0; kk < 8; kk++) {
            float4 a0 = *(const float4*)&As[kk][ty * 8];
            float4 a1 = *(const float4*)&As[kk][ty * 8 + 4];
            float4 b0 = *(const float4*)&Bs[kk][tx * 8];
            float4 b1 = *(const float4*)&Bs[kk][tx * 8 + 4];
            float a[8] = {a0.x, a0.y, a0.z, a0.w, a1.x, a1.y, a1.z, a1.w};
            float b[8] = {b0.x, b0.y, b0.z, b0.w, b1.x, b1.y, b1.z, b1.w};
#pragma unroll
            for (int i = 0; i < 8; i++)
#pragma unroll
                for (int j = 0; j < 8; j++) acc[i][j] += a[i] * b[j];
        }
    }

#pragma unroll
    for (int i = 0; i < 8; i++) {
        int r = rowBase + ty * 8 + i;
        if (r < NN) {
            float4 c0 = make_float4(acc[i][0], acc[i][1], acc[i][2], acc[i][3]);
            float4 c1 = make_float4(acc[i][4], acc[i][5], acc[i][6], acc[i][7]);
            *(float4*)(C + (size_t)r * P + colBase + tx * 8)     = c0;
            *(float4*)(C + (size_t)r * P + colBase + tx * 8 + 4) = c1;
        }
    }
}

// ---------------- per-node attention projections ---------------------------
__global__ __launch_bounds__(256) void alphas1_k(const float* __restrict__ a_src,
                                                 const float* __restrict__ a_dst) {
    int warp = (blockIdx.x * blockDim.x + threadIdx.x) >> 5;
    int lane = threadIdx.x & 31;
    if (warp >= NN) return;
    const float* hp = g_h1 + (size_t)warp * F1;
#pragma unroll
    for (int hd = 0; hd < NHEAD; hd++) {
        float v0 = hp[hd * 64 + lane], v1 = hp[hd * 64 + 32 + lane];
        float s = v0 * a_src[hd * 64 + lane] + v1 * a_src[hd * 64 + 32 + lane];
        float d = v0 * a_dst[hd * 64 + lane] + v1 * a_dst[hd * 64 + 32 + lane];
#pragma unroll
        for (int o = 16; o; o >>= 1) {
            s += __shfl_down_sync(0xffffffffu, s, o);
            d += __shfl_down_sync(0xffffffffu, d, o);
        }
        if (lane == 0) { g_as1[warp * NHEAD + hd] = s; g_ad1[warp * NHEAD + hd] = d; }
    }
}

__global__ __launch_bounds__(256) void alphas2_k(const float* __restrict__ a_src,
                                                 const float* __restrict__ a_dst) {
    int warp = (blockIdx.x * blockDim.x + threadIdx.x) >> 5;
    int lane = threadIdx.x & 31;
    if (warp >= NN) return;
    const float* hp = g_h2 + (size_t)warp * OUTC;
    float s = 0.f, d = 0.f;
#pragma unroll
    for (int q = 0; q < 4; q++) {
        int c = lane + q * 32;
        float v = hp[c];
        s += v * a_src[c];
        d += v * a_dst[c];
    }
#pragma unroll
    for (int o = 16; o; o >>= 1) {
        s += __shfl_down_sync(0xffffffffu, s, o);
        d += __shfl_down_sync(0xffffffffu, d, o);
    }
    if (lane == 0) { g_as2[warp] = s; g_ad2[warp] = d; }
}

// ---------------- fused per-dst softmax + aggregate + epilogue -------------
// L=0: blockDim 256 (one thread per channel of F1); L=1: blockDim 128.
template <int L>
__global__ __launch_bounds__(256) void gat_agg(const float* __restrict__ bias,
                                               float* __restrict__ outp) {
    constexpr int F = (L == 0) ? F1 : OUTC;
    constexpr int H = (L == 0) ? NHEAD : 1;
    const float* hin = (L == 0) ? g_h1 : g_h2;

    const int dst = blockIdx.x;
    const int off = g_off[dst];
    const int deg = g_off[dst + 1] - off;
    const int tid = threadIdx.x;

    __shared__ float s_inv[NHEAD];

    // ---- phase A: softmax over this node's incoming edges (warp 0 only) ----
    if (tid < 32) {
        const int lane = tid;
        if (L == 0) {
            float4 ad = *(const float4*)(g_ad1 + dst * 4);
            float m0 = NINF, m1 = NINF, m2 = NINF, m3 = NINF;
            for (int i = lane; i < deg; i += 32) {
                int src = g_ssrc[off + i];
                float4 as = *(const float4*)(g_as1 + src * 4);
                float v0 = as.x + ad.x; v0 = (v0 > 0.f) ? v0 : NEG * v0;
                float v1 = as.y + ad.y; v1 = (v1 > 0.f) ? v1 : NEG * v1;
                float v2 = as.z + ad.z; v2 = (v2 > 0.f) ? v2 : NEG * v2;
                float v3 = as.w + ad.w; v3 = (v3 > 0.f) ? v3 : NEG * v3;
                m0 = fmaxf(m0, v0); m1 = fmaxf(m1, v1);
                m2 = fmaxf(m2, v2); m3 = fmaxf(m3, v3);
            }
#pragma unroll
            for (int o = 16; o; o >>= 1) {
                m0 = fmaxf(m0, __shfl_xor_sync(0xffffffffu, m0, o));
                m1 = fmaxf(m1, __shfl_xor_sync(0xffffffffu, m1, o));
                m2 = fmaxf(m2, __shfl_xor_sync(0xffffffffu, m2, o));
                m3 = fmaxf(m3, __shfl_xor_sync(0xffffffffu, m3, o));
            }
            float s0 = 0.f, s1 = 0.f, s2 = 0.f, s3 = 0.f;
            for (int i = lane; i < deg; i += 32) {
                int src = g_ssrc[off + i];
                float4 as = *(const float4*)(g_as1 + src * 4);
                float v0 = as.x + ad.x; v0 = (v0 > 0.f) ? v0 : NEG * v0;
                float v1 = as.y + ad.y; v1 = (v1 > 0.f) ? v1 : NEG * v1;
                float v2 = as.z + ad.z; v2 = (v2 > 0.f) ? v2 : NEG * v2;
                float v3 = as.w + ad.w; v3 = (v3 > 0.f) ? v3 : NEG * v3;
                float e0 = __expf(v0 - m0), e1 = __expf(v1 - m1);
                float e2 = __expf(v2 - m2), e3 = __expf(v3 - m3);
                *(float4*)(g_alpha + (size_t)(off + i) * 4) = make_float4(e0, e1, e2, e3);
                s0 += e0; s1 += e1; s2 += e2; s3 += e3;
            }
#pragma unroll
            for (int o = 16; o; o >>= 1) {
                s0 += __shfl_xor_sync(0xffffffffu, s0, o);
                s1 += __shfl_xor_sync(0xffffffffu, s1, o);
                s2 += __shfl_xor_sync(0xffffffffu, s2, o);
                s3 += __shfl_xor_sync(0xffffffffu, s3, o);
            }
            if (lane == 0) {
                s_inv[0] = 1.f / s0; s_inv[1] = 1.f / s1;
                s_inv[2] = 1.f / s2; s_inv[3] = 1.f / s3;
            }
        } else {
            float adv = g_ad2[dst];
            float m = NINF;
            for (int i = lane; i < deg; i += 32) {
                float v = g_as2[g_ssrc[off + i]] + adv;
                v = (v > 0.f) ? v : NEG * v;
                m = fmaxf(m, v);
            }
#pragma unroll
            for (int o = 16; o; o >>= 1)
                m = fmaxf(m, __shfl_xor_sync(0xffffffffu, m, o));
            float s = 0.f;
            for (int i = lane; i < deg; i += 32) {
                float v = g_as2[g_ssrc[off + i]] + adv;
                v = (v > 0.f) ? v : NEG * v;
                float ex = __expf(v - m);
                g_alpha[off + i] = ex;
                s += ex;
            }
#pragma unroll
            for (int o = 16; o; o >>= 1)
                s += __shfl_xor_sync(0xffffffffu, s, o);
            if (lane == 0) s_inv[0] = 1.f / s;
        }
    }
    __syncthreads();

    // ---- phase B: gather-accumulate, one thread per output channel ----
    const int c = tid;
    const int hd = (L == 0) ? (c >> 6) : 0;
    float acc = 0.f;
    for (int i = 0; i < deg; i++) {
        int src = g_ssrc[off + i];                       // broadcast (L1 hit)
        float a = g_alpha[(size_t)(off + i) * H + hd];   // broadcast per head
        acc += a * hin[(size_t)src * F + c];             // coalesced 1KB gather
    }
    float r = acc * s_inv[hd] + bias[c];
    if (L == 0) {
        r = (r > 0.f) ? r : expm1f(r);
        g_out1[(size_t)dst * F + c] = r;
    } else {
        outp[(size_t)dst * F + c] = r;
    }
}

// ---------------- launch ---------------------------------------------------
extern "C" void kernel_launch(void* const* d_in, const int* in_sizes, int n_in,
                              void* d_out, int out_size) {
    const float* x   = (const float*)d_in[0];
    const int*   ei  = (const int*)d_in[1];   // int32 edge_index [2, E]
    const float* W1  = (const float*)d_in[2];
    const float* as1 = (const float*)d_in[3];
    const float* ad1 = (const float*)d_in[4];
    const float* b1  = (const float*)d_in[5];
    const float* W2  = (const float*)d_in[6];
    const float* as2 = (const float*)d_in[7];
    const float* ad2 = (const float*)d_in[8];
    const float* b2  = (const float*)d_in[9];
    float*       out = (float*)d_out;

    const int T = 256;

    // CSR build (graph identical for both layers)
    zero_cnt<<<(NN + T - 1) / T, T>>>();
    csr_count<<<(ET + T - 1) / T, T>>>(ei);
    csr_scan<<<1, 1024>>>();
    csr_scatter<<<(ET + T - 1) / T, T>>>(ei);

    // ---- layer 1 ----
    sgemm<0><<<dim3(F1 / 128, (NN + 127) / 128), T>>>(x, W1);
    alphas1_k<<<(NN * 32 + T - 1) / T, T>>>(as1, ad1);
    gat_agg<0><<<NN, 256>>>(b1, nullptr);

    // ---- layer 2 ----
    sgemm<1><<<dim3(OUTC / 128, (NN + 127) / 128), T>>>(nullptr, W2);
    alphas2_k<<<(NN * 32 + T - 1) / T, T>>>(as2, ad2);
    gat_agg<1><<<NN, 128>>>(b2, out);
}